// round 4
// baseline (speedup 1.0000x reference)
#include <cuda_runtime.h>

#define NN 100000
#define EE 1600000
#define DD 64
#define GG 128
#define BN_EPS 1e-5f
#define SCAN_BS 1024
#define STAT_BLOCKS 512

// ---------------- device scratch (static: no allocation allowed) ----------------
__device__ int       g_deg[NN];
__device__ float     g_dinv[NN];
__device__ int       g_esrc[EE];            // CSR edge sources, grouped by dst
__device__ int       g_rowstart[NN + 1];
__device__ int       g_cursor[NN];
__device__ int       g_bsum[128];
__device__ int       g_boff[128];
__device__ float     g_t[(size_t)NN * DD];    // post-GEMM features (pre-scaled by dinv[row])
__device__ float     g_acc[(size_t)NN * DD];  // aggregated features
__device__ float     g_h[(size_t)NN * DD];    // layer activations
__device__ float     g_psum[STAT_BLOCKS * DD];  // BN partial sums
__device__ float     g_psq[STAT_BLOCKS * DD];   // BN partial sum-of-squares
__device__ float     g_scale[DD];
__device__ float     g_shift[DD];
__device__ float     g_gcnt[GG];

// ---------------- init ----------------
__global__ void init_k(float* out, int N) {
    int i = blockIdx.x * blockDim.x + threadIdx.x;
    if (i < N) g_deg[i] = 0;
    if (i < GG) g_gcnt[i] = 0.f;
    if (i < GG * DD) out[i] = 0.f;
}

// ---------------- degree histogram over dst (int32 indices!) ----------------
__global__ void deg_k(const int* __restrict__ dst, int E) {
    int e = blockIdx.x * blockDim.x + threadIdx.x;
    if (e < E) atomicAdd(&g_deg[dst[e]], 1);
}

__global__ void dinv_k(int N) {
    int i = blockIdx.x * blockDim.x + threadIdx.x;
    if (i < N) g_dinv[i] = rsqrtf((float)(g_deg[i] + 1));  // +1 self loop
}

// ---------------- 3-phase exclusive scan of g_deg -> g_rowstart ----------------
__global__ void scan1_k(int N) {
    int i = blockIdx.x * SCAN_BS + threadIdx.x;
    int v = (i < N) ? g_deg[i] : 0;
    int lane = threadIdx.x & 31, wid = threadIdx.x >> 5;
    int x = v;
    #pragma unroll
    for (int o = 1; o < 32; o <<= 1) {
        int y = __shfl_up_sync(0xffffffffu, x, o);
        if (lane >= o) x += y;
    }
    __shared__ int wsum[32];
    if (lane == 31) wsum[wid] = x;
    __syncthreads();
    if (wid == 0) {
        int y = wsum[lane];
        #pragma unroll
        for (int o = 1; o < 32; o <<= 1) {
            int z = __shfl_up_sync(0xffffffffu, y, o);
            if (lane >= o) y += z;
        }
        wsum[lane] = y;
    }
    __syncthreads();
    int incl = x + (wid > 0 ? wsum[wid - 1] : 0);
    if (i < N) g_rowstart[i] = incl - v;  // block-local exclusive
    if (threadIdx.x == SCAN_BS - 1) g_bsum[blockIdx.x] = incl;
}

__global__ void scan2_k(int nb) {
    __shared__ int s[128];
    int t = threadIdx.x;
    s[t] = (t < nb) ? g_bsum[t] : 0;
    __syncthreads();
    if (t == 0) {
        int run = 0;
        for (int i = 0; i < nb; i++) { int v = s[i]; s[i] = run; run += v; }
    }
    __syncthreads();
    if (t < nb) g_boff[t] = s[t];
}

__global__ void scan3_k(int N, int E) {
    int i = blockIdx.x * blockDim.x + threadIdx.x;
    if (i < N) {
        int rs = g_rowstart[i] + g_boff[i >> 10];
        g_rowstart[i] = rs;
        g_cursor[i] = rs;
    }
    if (i == 0) g_rowstart[N] = E;
}

// ---------------- permute edges into CSR (int32 indices) ----------------
__global__ void perm_k(const int* __restrict__ src, const int* __restrict__ dst, int E) {
    int e = blockIdx.x * blockDim.x + threadIdx.x;
    if (e < E) {
        int d = dst[e];
        int pos = atomicAdd(&g_cursor[d], 1);
        g_esrc[pos] = src[e];
    }
}

// ---------------- 64-wide GEMM: g_t[n] = dinv[n] * (in @ W)[n] ----------------
__global__ void gemm64_k(const float* __restrict__ X, const float* __restrict__ W,
                         int layer, int N) {
    const float* in = (layer == 0) ? X : g_h;
    __shared__ __align__(16) float As[64][64]; // As[k][r]
    __shared__ __align__(16) float Bs[64][64]; // Bs[k][n]
    int t = threadIdx.x;
    int row0 = blockIdx.x * 64;

    #pragma unroll 4
    for (int i = t; i < 1024; i += 256)
        ((float4*)Bs)[i] = ((const float4*)W)[i];

    #pragma unroll 4
    for (int i = t; i < 1024; i += 256) {
        int r = i >> 4;
        int kc = (i & 15) << 2;
        int gr = row0 + r;
        float4 v = make_float4(0.f, 0.f, 0.f, 0.f);
        if (gr < N) v = ((const float4*)(in + (size_t)gr * 64))[i & 15];
        As[kc + 0][r] = v.x;
        As[kc + 1][r] = v.y;
        As[kc + 2][r] = v.z;
        As[kc + 3][r] = v.w;
    }
    __syncthreads();

    int tx = t & 15, ty = t >> 4;
    int r0 = ty << 2, c0 = tx << 2;
    float acc[4][4];
    #pragma unroll
    for (int i = 0; i < 4; i++)
        #pragma unroll
        for (int j = 0; j < 4; j++) acc[i][j] = 0.f;

    #pragma unroll
    for (int k = 0; k < 64; k++) {
        float4 a = *(const float4*)&As[k][r0];
        float4 b = *(const float4*)&Bs[k][c0];
        acc[0][0] += a.x * b.x; acc[0][1] += a.x * b.y; acc[0][2] += a.x * b.z; acc[0][3] += a.x * b.w;
        acc[1][0] += a.y * b.x; acc[1][1] += a.y * b.y; acc[1][2] += a.y * b.z; acc[1][3] += a.y * b.w;
        acc[2][0] += a.z * b.x; acc[2][1] += a.z * b.y; acc[2][2] += a.z * b.z; acc[2][3] += a.z * b.w;
        acc[3][0] += a.w * b.x; acc[3][1] += a.w * b.y; acc[3][2] += a.w * b.z; acc[3][3] += a.w * b.w;
    }

    #pragma unroll
    for (int i = 0; i < 4; i++) {
        int gr = row0 + r0 + i;
        if (gr < N) {
            float dv = g_dinv[gr];
            *(float4*)(g_t + (size_t)gr * 64 + c0) =
                make_float4(acc[i][0] * dv, acc[i][1] * dv, acc[i][2] * dv, acc[i][3] * dv);
        }
    }
}

// ---------------- CSR gather: acc[d] = dinv[d]*(sum g_t[src] + g_t[d]) + b ----
__global__ void gather_k(const float* __restrict__ b, int N) {
    int idx = blockIdx.x * blockDim.x + threadIdx.x;
    int node = idx >> 4;
    if (node >= N) return;
    int lane = idx & 15;
    float4 bb = ((const float4*)b)[lane];

    int beg = g_rowstart[node];
    int end = g_rowstart[node + 1];

    // self loop term (g_t already scaled by dinv[node])
    float4 acc = ((const float4*)(g_t + (size_t)node * 64))[lane];

    int k = beg;
    #pragma unroll 1
    for (; k + 4 <= end; k += 4) {
        int s0 = g_esrc[k + 0];
        int s1 = g_esrc[k + 1];
        int s2 = g_esrc[k + 2];
        int s3 = g_esrc[k + 3];
        float4 v0 = __ldg(((const float4*)(g_t + (size_t)s0 * 64)) + lane);
        float4 v1 = __ldg(((const float4*)(g_t + (size_t)s1 * 64)) + lane);
        float4 v2 = __ldg(((const float4*)(g_t + (size_t)s2 * 64)) + lane);
        float4 v3 = __ldg(((const float4*)(g_t + (size_t)s3 * 64)) + lane);
        acc.x += v0.x + v1.x + v2.x + v3.x;
        acc.y += v0.y + v1.y + v2.y + v3.y;
        acc.z += v0.z + v1.z + v2.z + v3.z;
        acc.w += v0.w + v1.w + v2.w + v3.w;
    }
    for (; k < end; k++) {
        int s = g_esrc[k];
        float4 v = __ldg(((const float4*)(g_t + (size_t)s * 64)) + lane);
        acc.x += v.x; acc.y += v.y; acc.z += v.z; acc.w += v.w;
    }

    float dv = g_dinv[node];
    acc.x = acc.x * dv + bb.x;
    acc.y = acc.y * dv + bb.y;
    acc.z = acc.z * dv + bb.z;
    acc.w = acc.w * dv + bb.w;
    ((float4*)(g_acc + (size_t)node * 64))[lane] = acc;
}

// ---------------- BN statistics over g_acc: per-block float partials ----------
__global__ void stats_k(int N) {
    int cg = threadIdx.x & 15;   // float4 column group
    int rib = threadIdx.x >> 4;  // 0..15
    float ls0 = 0.f, ls1 = 0.f, ls2 = 0.f, ls3 = 0.f;
    float lq0 = 0.f, lq1 = 0.f, lq2 = 0.f, lq3 = 0.f;

    for (int n = blockIdx.x * 16 + rib; n < N; n += gridDim.x * 16) {
        float4 a = ((const float4*)(g_acc + (size_t)n * 64))[cg];
        ls0 += a.x; lq0 += a.x * a.x;
        ls1 += a.y; lq1 += a.y * a.y;
        ls2 += a.z; lq2 += a.z * a.z;
        ls3 += a.w; lq3 += a.w * a.w;
    }

    __shared__ float ssum[16][64];
    __shared__ float ssq[16][64];
    int c = cg * 4;
    ssum[rib][c + 0] = ls0; ssq[rib][c + 0] = lq0;
    ssum[rib][c + 1] = ls1; ssq[rib][c + 1] = lq1;
    ssum[rib][c + 2] = ls2; ssq[rib][c + 2] = lq2;
    ssum[rib][c + 3] = ls3; ssq[rib][c + 3] = lq3;
    __syncthreads();

    if (threadIdx.x < 64) {
        float s = 0.f, q = 0.f;
        #pragma unroll
        for (int r = 0; r < 16; r++) { s += ssum[r][threadIdx.x]; q += ssq[r][threadIdx.x]; }
        g_psum[blockIdx.x * DD + threadIdx.x] = s;
        g_psq[blockIdx.x * DD + threadIdx.x] = q;
    }
}

// ---------------- BN finalize: reduce partials, build scale/shift -------------
__global__ void bn_final_k(const float* __restrict__ gamma,
                           const float* __restrict__ beta, int N) {
    int c = threadIdx.x;
    if (c < DD) {
        float s = 0.f, q = 0.f;
        for (int b = 0; b < STAT_BLOCKS; b++) {
            s += g_psum[b * DD + c];
            q += g_psq[b * DD + c];
        }
        float inv_n = 1.0f / (float)N;
        float m = s * inv_n;
        float v = q * inv_n - m * m;
        float sc = gamma[c] * rsqrtf(v + BN_EPS);
        g_scale[c] = sc;
        g_shift[c] = beta[c] - m * sc;
    }
}

// ---------------- BN apply + ReLU -> g_h ----------------
__global__ void bn_relu_k(int N) {
    int i = blockIdx.x * blockDim.x + threadIdx.x;
    if (i >= N * 16) return;
    int cg = i & 15;
    float4 sc = ((const float4*)g_scale)[cg];
    float4 sh = ((const float4*)g_shift)[cg];
    float4 v = ((const float4*)g_acc)[i];
    v.x = fmaxf(v.x * sc.x + sh.x, 0.f);
    v.y = fmaxf(v.y * sc.y + sh.y, 0.f);
    v.z = fmaxf(v.z * sc.z + sh.z, 0.f);
    v.w = fmaxf(v.w * sc.w + sh.w, 0.f);
    ((float4*)g_h)[i] = v;
}

// ---------------- mean pool: batch is sorted int32 -> run-length accumulate ---
__global__ void pool_k(const int* __restrict__ batch, float* __restrict__ out, int N) {
    int col = threadIdx.x;  // 64 threads
    int start = blockIdx.x * 256;
    if (start >= N) return;
    int end = min(start + 256, N);
    int g = batch[start];
    float s = 0.f;
    float cnt = 0.f;
    for (int n = start; n < end; n++) {
        int gn = batch[n];
        if (gn != g) {
            atomicAdd(&out[g * 64 + col], s);
            if (col == 0) atomicAdd(&g_gcnt[g], cnt);
            s = 0.f; cnt = 0.f; g = gn;
        }
        s += g_h[(size_t)n * 64 + col];
        cnt += 1.f;
    }
    atomicAdd(&out[g * 64 + col], s);
    if (col == 0) atomicAdd(&g_gcnt[g], cnt);
}

__global__ void scale_out_k(float* out) {
    int i = blockIdx.x * blockDim.x + threadIdx.x;
    if (i < GG * DD) {
        float c = g_gcnt[i >> 6];
        out[i] /= fmaxf(c, 1.f);
    }
}

// ---------------- host launch ----------------
extern "C" void kernel_launch(void* const* d_in, const int* in_sizes, int n_in,
                              void* d_out, int out_size) {
    const float* x      = (const float*)d_in[0];
    const int*   ei     = (const int*)d_in[1];     // int32! (JAX x64 disabled)
    const int*   batch  = (const int*)d_in[2];     // int32!
    const float* Ws     = (const float*)d_in[3];
    const float* bs     = (const float*)d_in[4];
    const float* gammas = (const float*)d_in[5];
    const float* betas  = (const float*)d_in[6];
    float*       out    = (float*)d_out;

    int N = in_sizes[0] / DD;   // 100000
    int E = in_sizes[1] / 2;    // 1600000
    const int* src = ei;
    const int* dst = ei + E;

    int tb = 256;
    int nBlk  = (N + tb - 1) / tb;
    int eBlk  = (E + tb - 1) / tb;
    int ndBlk = (N * 16 + tb - 1) / tb;
    int gaBlk = (N * 16 + tb - 1) / tb;
    int gmBlk = (N + 63) / 64;
    int nScanBlk = (N + SCAN_BS - 1) / SCAN_BS;

    init_k<<<nBlk, tb>>>(out, N);
    deg_k<<<eBlk, tb>>>(dst, E);
    dinv_k<<<nBlk, tb>>>(N);
    scan1_k<<<nScanBlk, SCAN_BS>>>(N);
    scan2_k<<<1, 128>>>(nScanBlk);
    scan3_k<<<nBlk, tb>>>(N, E);
    perm_k<<<eBlk, tb>>>(src, dst, E);

    for (int l = 0; l < 3; l++) {
        gemm64_k<<<gmBlk, 256>>>(x, Ws + l * DD * DD, l, N);
        gather_k<<<gaBlk, tb>>>(bs + l * DD, N);
        stats_k<<<STAT_BLOCKS, 256>>>(N);
        bn_final_k<<<1, 64>>>(gammas + l * DD, betas + l * DD, N);
        bn_relu_k<<<ndBlk, tb>>>(N);
    }

    pool_k<<<(N + 255) / 256, 64>>>(batch, out, N);
    scale_out_k<<<(GG * DD + tb - 1) / tb, tb>>>(out);
}

// round 5
// speedup vs baseline: 1.2242x; 1.2242x over previous
#include <cuda_runtime.h>

#define NN 100000
#define EE 1600000
#define DD 64
#define GG 128
#define BN_EPS 1e-5f
#define SCAN_BS 1024
#define GA_BLOCKS ((NN * 16 + 255) / 256)   // 6250

// ---------------- device scratch (static: no allocation allowed) ----------------
__device__ int       g_deg[NN];
__device__ float     g_dinv[NN];
__device__ int       g_esrc[EE];              // CSR edge sources, grouped by dst
__device__ int       g_rowstart[NN + 1];
__device__ int       g_cursor[NN];
__device__ int       g_bsum[128];
__device__ int       g_boff[128];
__device__ float     g_t[(size_t)NN * DD];    // post-GEMM features (pre-scaled by dinv[row])
__device__ float     g_acc[(size_t)NN * DD];  // aggregated (pre-BN) features
__device__ float     g_psum[GA_BLOCKS * DD];  // BN partial sums
__device__ float     g_psq[GA_BLOCKS * DD];   // BN partial sum-of-squares
__device__ float     g_scale[DD];
__device__ float     g_shift[DD];
__device__ float     g_gcnt[GG];

// ---------------- init ----------------
__global__ void init_k(float* out, int N) {
    int i = blockIdx.x * blockDim.x + threadIdx.x;
    if (i < N) g_deg[i] = 0;
    if (i < GG) g_gcnt[i] = 0.f;
    if (i < GG * DD) out[i] = 0.f;
}

// ---------------- degree histogram over dst ----------------
__global__ void deg_k(const int* __restrict__ dst, int E) {
    int e = blockIdx.x * blockDim.x + threadIdx.x;
    if (e < E) atomicAdd(&g_deg[dst[e]], 1);
}

// ---------------- scan phase 1 (also computes dinv) ----------------
__global__ void scan1_k(int N) {
    int i = blockIdx.x * SCAN_BS + threadIdx.x;
    int v = (i < N) ? g_deg[i] : 0;
    if (i < N) g_dinv[i] = rsqrtf((float)(v + 1));  // +1 self loop
    int lane = threadIdx.x & 31, wid = threadIdx.x >> 5;
    int x = v;
    #pragma unroll
    for (int o = 1; o < 32; o <<= 1) {
        int y = __shfl_up_sync(0xffffffffu, x, o);
        if (lane >= o) x += y;
    }
    __shared__ int wsum[32];
    if (lane == 31) wsum[wid] = x;
    __syncthreads();
    if (wid == 0) {
        int y = wsum[lane];
        #pragma unroll
        for (int o = 1; o < 32; o <<= 1) {
            int z = __shfl_up_sync(0xffffffffu, y, o);
            if (lane >= o) y += z;
        }
        wsum[lane] = y;
    }
    __syncthreads();
    int incl = x + (wid > 0 ? wsum[wid - 1] : 0);
    if (i < N) g_rowstart[i] = incl - v;  // block-local exclusive
    if (threadIdx.x == SCAN_BS - 1) g_bsum[blockIdx.x] = incl;
}

__global__ void scan2_k(int nb) {
    __shared__ int s[128];
    int t = threadIdx.x;
    s[t] = (t < nb) ? g_bsum[t] : 0;
    __syncthreads();
    if (t == 0) {
        int run = 0;
        for (int i = 0; i < nb; i++) { int v = s[i]; s[i] = run; run += v; }
    }
    __syncthreads();
    if (t < nb) g_boff[t] = s[t];
}

__global__ void scan3_k(int N, int E) {
    int i = blockIdx.x * blockDim.x + threadIdx.x;
    if (i < N) {
        int rs = g_rowstart[i] + g_boff[i >> 10];
        g_rowstart[i] = rs;
        g_cursor[i] = rs;
    }
    if (i == 0) g_rowstart[N] = E;
}

// ---------------- permute edges into CSR ----------------
__global__ void perm_k(const int* __restrict__ src, const int* __restrict__ dst, int E) {
    int e = blockIdx.x * blockDim.x + threadIdx.x;
    if (e < E) {
        int d = dst[e];
        int pos = atomicAdd(&g_cursor[d], 1);
        g_esrc[pos] = src[e];
    }
}

// ---------------- GEMM: g_t[n] = dinv[n] * (A @ W)[n]
// A = x (layer 0) or relu(g_acc * scale + shift) (layers > 0, fused BN+ReLU)
__global__ void gemm64_k(const float* __restrict__ X, const float* __restrict__ W,
                         int layer, int N) {
    __shared__ __align__(16) float As[64][64]; // As[k][r]
    __shared__ __align__(16) float Bs[64][64]; // Bs[k][n]
    int t = threadIdx.x;
    int row0 = blockIdx.x * 64;

    #pragma unroll 4
    for (int i = t; i < 1024; i += 256)
        ((float4*)Bs)[i] = ((const float4*)W)[i];

    if (layer == 0) {
        #pragma unroll 4
        for (int i = t; i < 1024; i += 256) {
            int r = i >> 4;
            int kc = (i & 15) << 2;
            int gr = row0 + r;
            float4 v = make_float4(0.f, 0.f, 0.f, 0.f);
            if (gr < N) v = ((const float4*)(X + (size_t)gr * 64))[i & 15];
            As[kc + 0][r] = v.x;
            As[kc + 1][r] = v.y;
            As[kc + 2][r] = v.z;
            As[kc + 3][r] = v.w;
        }
    } else {
        #pragma unroll 4
        for (int i = t; i < 1024; i += 256) {
            int r = i >> 4;
            int kc = (i & 15) << 2;
            int gr = row0 + r;
            float4 v = make_float4(0.f, 0.f, 0.f, 0.f);
            if (gr < N) {
                float4 a = ((const float4*)(g_acc + (size_t)gr * 64))[i & 15];
                float4 sc = ((const float4*)g_scale)[i & 15];
                float4 sh = ((const float4*)g_shift)[i & 15];
                v.x = fmaxf(a.x * sc.x + sh.x, 0.f);
                v.y = fmaxf(a.y * sc.y + sh.y, 0.f);
                v.z = fmaxf(a.z * sc.z + sh.z, 0.f);
                v.w = fmaxf(a.w * sc.w + sh.w, 0.f);
            }
            As[kc + 0][r] = v.x;
            As[kc + 1][r] = v.y;
            As[kc + 2][r] = v.z;
            As[kc + 3][r] = v.w;
        }
    }
    __syncthreads();

    int tx = t & 15, ty = t >> 4;
    int r0 = ty << 2, c0 = tx << 2;
    float acc[4][4];
    #pragma unroll
    for (int i = 0; i < 4; i++)
        #pragma unroll
        for (int j = 0; j < 4; j++) acc[i][j] = 0.f;

    #pragma unroll
    for (int k = 0; k < 64; k++) {
        float4 a = *(const float4*)&As[k][r0];
        float4 b = *(const float4*)&Bs[k][c0];
        acc[0][0] += a.x * b.x; acc[0][1] += a.x * b.y; acc[0][2] += a.x * b.z; acc[0][3] += a.x * b.w;
        acc[1][0] += a.y * b.x; acc[1][1] += a.y * b.y; acc[1][2] += a.y * b.z; acc[1][3] += a.y * b.w;
        acc[2][0] += a.z * b.x; acc[2][1] += a.z * b.y; acc[2][2] += a.z * b.z; acc[2][3] += a.z * b.w;
        acc[3][0] += a.w * b.x; acc[3][1] += a.w * b.y; acc[3][2] += a.w * b.z; acc[3][3] += a.w * b.w;
    }

    #pragma unroll
    for (int i = 0; i < 4; i++) {
        int gr = row0 + r0 + i;
        if (gr < N) {
            float dv = g_dinv[gr];
            *(float4*)(g_t + (size_t)gr * 64 + c0) =
                make_float4(acc[i][0] * dv, acc[i][1] * dv, acc[i][2] * dv, acc[i][3] * dv);
        }
    }
}

// ---------------- CSR gather + fused BN partial statistics ----------------
// acc[d] = dinv[d]*(sum g_t[src] + g_t[d]) + b ;  block writes BN partials
__global__ void gather_k(const float* __restrict__ b, int N) {
    int idx = blockIdx.x * blockDim.x + threadIdx.x;
    int node = idx >> 4;
    int lane = idx & 15;
    bool valid = (node < N);

    float4 acc = make_float4(0.f, 0.f, 0.f, 0.f);
    if (valid) {
        float4 bb = ((const float4*)b)[lane];
        int beg = g_rowstart[node];
        int end = g_rowstart[node + 1];

        // self loop term (g_t already scaled by dinv[node])
        acc = ((const float4*)(g_t + (size_t)node * 64))[lane];

        int k = beg;
        #pragma unroll 1
        for (; k + 8 <= end; k += 8) {
            int s0 = g_esrc[k + 0], s1 = g_esrc[k + 1], s2 = g_esrc[k + 2], s3 = g_esrc[k + 3];
            int s4 = g_esrc[k + 4], s5 = g_esrc[k + 5], s6 = g_esrc[k + 6], s7 = g_esrc[k + 7];
            float4 v0 = __ldg(((const float4*)(g_t + (size_t)s0 * 64)) + lane);
            float4 v1 = __ldg(((const float4*)(g_t + (size_t)s1 * 64)) + lane);
            float4 v2 = __ldg(((const float4*)(g_t + (size_t)s2 * 64)) + lane);
            float4 v3 = __ldg(((const float4*)(g_t + (size_t)s3 * 64)) + lane);
            float4 v4 = __ldg(((const float4*)(g_t + (size_t)s4 * 64)) + lane);
            float4 v5 = __ldg(((const float4*)(g_t + (size_t)s5 * 64)) + lane);
            float4 v6 = __ldg(((const float4*)(g_t + (size_t)s6 * 64)) + lane);
            float4 v7 = __ldg(((const float4*)(g_t + (size_t)s7 * 64)) + lane);
            acc.x += (v0.x + v1.x) + (v2.x + v3.x) + (v4.x + v5.x) + (v6.x + v7.x);
            acc.y += (v0.y + v1.y) + (v2.y + v3.y) + (v4.y + v5.y) + (v6.y + v7.y);
            acc.z += (v0.z + v1.z) + (v2.z + v3.z) + (v4.z + v5.z) + (v6.z + v7.z);
            acc.w += (v0.w + v1.w) + (v2.w + v3.w) + (v4.w + v5.w) + (v6.w + v7.w);
        }
        for (; k < end; k++) {
            int s = g_esrc[k];
            float4 v = __ldg(((const float4*)(g_t + (size_t)s * 64)) + lane);
            acc.x += v.x; acc.y += v.y; acc.z += v.z; acc.w += v.w;
        }

        float dv = g_dinv[node];
        acc.x = acc.x * dv + bb.x;
        acc.y = acc.y * dv + bb.y;
        acc.z = acc.z * dv + bb.z;
        acc.w = acc.w * dv + bb.w;
        ((float4*)(g_acc + (size_t)node * 64))[lane] = acc;
    }

    // --- fused BN partial stats: reduce 16 nodes x 64 cols within block ---
    __shared__ float ssum[16][64];
    __shared__ float ssq[16][64];
    int rib = threadIdx.x >> 4;   // node slot in block
    int c = lane * 4;
    ssum[rib][c + 0] = acc.x; ssq[rib][c + 0] = acc.x * acc.x;
    ssum[rib][c + 1] = acc.y; ssq[rib][c + 1] = acc.y * acc.y;
    ssum[rib][c + 2] = acc.z; ssq[rib][c + 2] = acc.z * acc.z;
    ssum[rib][c + 3] = acc.w; ssq[rib][c + 3] = acc.w * acc.w;
    __syncthreads();

    if (threadIdx.x < 64) {
        float s = 0.f, q = 0.f;
        #pragma unroll
        for (int r = 0; r < 16; r++) { s += ssum[r][threadIdx.x]; q += ssq[r][threadIdx.x]; }
        g_psum[blockIdx.x * DD + threadIdx.x] = s;
        g_psq[blockIdx.x * DD + threadIdx.x] = q;
    }
}

// ---------------- BN finalize: 64 blocks, one column each ----------------
__global__ void bn_final_k(const float* __restrict__ gamma,
                           const float* __restrict__ beta, int N, int nblocks) {
    int c = blockIdx.x;      // column
    int t = threadIdx.x;     // 256 threads
    float s = 0.f, q = 0.f;
    for (int b = t; b < nblocks; b += 256) {
        s += g_psum[b * DD + c];
        q += g_psq[b * DD + c];
    }
    __shared__ float sh_s[256], sh_q[256];
    sh_s[t] = s; sh_q[t] = q;
    __syncthreads();
    #pragma unroll
    for (int o = 128; o > 0; o >>= 1) {
        if (t < o) { sh_s[t] += sh_s[t + o]; sh_q[t] += sh_q[t + o]; }
        __syncthreads();
    }
    if (t == 0) {
        float inv_n = 1.0f / (float)N;
        float m = sh_s[0] * inv_n;
        float v = sh_q[0] * inv_n - m * m;
        float sc = gamma[c] * rsqrtf(v + BN_EPS);
        g_scale[c] = sc;
        g_shift[c] = beta[c] - m * sc;
    }
}

// ---------------- mean pool (fused BN+ReLU of last layer) ----------------
__global__ void pool_k(const int* __restrict__ batch, float* __restrict__ out, int N) {
    int col = threadIdx.x;  // 64 threads
    int start = blockIdx.x * 128;
    if (start >= N) return;
    int end = min(start + 128, N);
    float sc = g_scale[col];
    float sh = g_shift[col];
    int g = batch[start];
    float s = 0.f;
    float cnt = 0.f;
    for (int n = start; n < end; n++) {
        int gn = batch[n];
        if (gn != g) {
            atomicAdd(&out[g * 64 + col], s);
            if (col == 0) atomicAdd(&g_gcnt[g], cnt);
            s = 0.f; cnt = 0.f; g = gn;
        }
        float a = g_acc[(size_t)n * 64 + col];
        s += fmaxf(a * sc + sh, 0.f);
        cnt += 1.f;
    }
    atomicAdd(&out[g * 64 + col], s);
    if (col == 0) atomicAdd(&g_gcnt[g], cnt);
}

__global__ void scale_out_k(float* out) {
    int i = blockIdx.x * blockDim.x + threadIdx.x;
    if (i < GG * DD) {
        float c = g_gcnt[i >> 6];
        out[i] /= fmaxf(c, 1.f);
    }
}

// ---------------- host launch ----------------
extern "C" void kernel_launch(void* const* d_in, const int* in_sizes, int n_in,
                              void* d_out, int out_size) {
    const float* x      = (const float*)d_in[0];
    const int*   ei     = (const int*)d_in[1];     // int32 (JAX x64 disabled)
    const int*   batch  = (const int*)d_in[2];     // int32
    const float* Ws     = (const float*)d_in[3];
    const float* bs     = (const float*)d_in[4];
    const float* gammas = (const float*)d_in[5];
    const float* betas  = (const float*)d_in[6];
    float*       out    = (float*)d_out;

    int N = in_sizes[0] / DD;   // 100000
    int E = in_sizes[1] / 2;    // 1600000
    const int* src = ei;
    const int* dst = ei + E;

    int tb = 256;
    int nBlk  = (N + tb - 1) / tb;
    int eBlk  = (E + tb - 1) / tb;
    int gaBlk = (N * 16 + tb - 1) / tb;
    int gmBlk = (N + 63) / 64;
    int nScanBlk = (N + SCAN_BS - 1) / SCAN_BS;

    init_k<<<nBlk, tb>>>(out, N);
    deg_k<<<eBlk, tb>>>(dst, E);
    scan1_k<<<nScanBlk, SCAN_BS>>>(N);
    scan2_k<<<1, 128>>>(nScanBlk);
    scan3_k<<<nBlk, tb>>>(N, E);
    perm_k<<<eBlk, tb>>>(src, dst, E);

    for (int l = 0; l < 3; l++) {
        gemm64_k<<<gmBlk, 256>>>(x, Ws + l * DD * DD, l, N);
        gather_k<<<gaBlk, tb>>>(bs + l * DD, N);
        bn_final_k<<<64, 256>>>(gammas + l * DD, betas + l * DD, N, gaBlk);
    }

    pool_k<<<(N + 127) / 128, 64>>>(batch, out, N);
    scale_out_k<<<(GG * DD + tb - 1) / tb, tb>>>(out);
}

// round 6
// speedup vs baseline: 1.3937x; 1.1384x over previous
#include <cuda_runtime.h>
#include <cuda_fp16.h>

#define NN 100000
#define EE 1600000
#define DD 64
#define GG 128
#define BN_EPS 1e-5f
#define SCAN_BS 1024
#define GA_BLOCKS ((NN * 8 + 255) / 256)   // 3125

// ---------------- device scratch (static: no allocation allowed) ----------------
__device__ int       g_deg[NN];
__device__ float     g_dinv[NN];
__device__ int       g_esrc[EE];              // CSR edge sources, grouped by dst
__device__ int       g_rowstart[NN + 1];
__device__ int       g_cursor[NN];
__device__ int       g_bsum[128];
__device__ __half    g_t[(size_t)NN * DD];    // post-GEMM features, fp16, pre-scaled by dinv[row]
__device__ float     g_acc[(size_t)NN * DD];  // aggregated (pre-BN) features, fp32
__device__ float     g_psum[GA_BLOCKS * DD];  // BN partial sums
__device__ float     g_psq[GA_BLOCKS * DD];   // BN partial sum-of-squares
__device__ float     g_scale[DD];
__device__ float     g_shift[DD];
__device__ float     g_gcnt[GG];

// ---------------- f32x2 packed helpers ----------------
__device__ __forceinline__ unsigned long long pk2(float lo, float hi) {
    unsigned long long r;
    asm("mov.b64 %0, {%1, %2};" : "=l"(r) : "f"(lo), "f"(hi));
    return r;
}
__device__ __forceinline__ void fma2(unsigned long long& d,
                                     unsigned long long a, unsigned long long b) {
    asm("fma.rn.f32x2 %0, %1, %2, %0;" : "+l"(d) : "l"(a), "l"(b));
}
__device__ __forceinline__ float2 upk2(unsigned long long v) {
    float2 f;
    asm("mov.b64 {%0, %1}, %2;" : "=f"(f.x), "=f"(f.y) : "l"(v));
    return f;
}

// ---------------- init ----------------
__global__ void init_k(float* out, int N) {
    int i = blockIdx.x * blockDim.x + threadIdx.x;
    if (i < N) g_deg[i] = 0;
    if (i < GG) g_gcnt[i] = 0.f;
    if (i < GG * DD) out[i] = 0.f;
}

// ---------------- degree histogram over dst ----------------
__global__ void deg_k(const int* __restrict__ dst, int E) {
    int e = blockIdx.x * blockDim.x + threadIdx.x;
    if (e < E) atomicAdd(&g_deg[dst[e]], 1);
}

// ---------------- scan phase 1 (also computes dinv) ----------------
__global__ void scan1_k(int N) {
    int i = blockIdx.x * SCAN_BS + threadIdx.x;
    int v = (i < N) ? g_deg[i] : 0;
    if (i < N) g_dinv[i] = rsqrtf((float)(v + 1));  // +1 self loop
    int lane = threadIdx.x & 31, wid = threadIdx.x >> 5;
    int x = v;
    #pragma unroll
    for (int o = 1; o < 32; o <<= 1) {
        int y = __shfl_up_sync(0xffffffffu, x, o);
        if (lane >= o) x += y;
    }
    __shared__ int wsum[32];
    if (lane == 31) wsum[wid] = x;
    __syncthreads();
    if (wid == 0) {
        int y = wsum[lane];
        #pragma unroll
        for (int o = 1; o < 32; o <<= 1) {
            int z = __shfl_up_sync(0xffffffffu, y, o);
            if (lane >= o) y += z;
        }
        wsum[lane] = y;
    }
    __syncthreads();
    int incl = x + (wid > 0 ? wsum[wid - 1] : 0);
    if (i < N) g_rowstart[i] = incl - v;  // block-local exclusive
    if (threadIdx.x == SCAN_BS - 1) g_bsum[blockIdx.x] = incl;
}

// ---------------- scan phase 2+3 merged: per-block redundant prefix ----------
__global__ void scan3_k(int N, int E, int nb) {
    __shared__ int pre[128];
    int t = threadIdx.x;
    if (t < 128) pre[t] = (t < nb) ? g_bsum[t] : 0;
    __syncthreads();
    if (t == 0) {
        int run = 0;
        for (int i = 0; i < nb; i++) { int v = pre[i]; pre[i] = run; run += v; }
    }
    __syncthreads();
    int i = blockIdx.x * blockDim.x + t;
    if (i < N) {
        int rs = g_rowstart[i] + pre[i >> 10];
        g_rowstart[i] = rs;
        g_cursor[i] = rs;
    }
    if (i == 0) g_rowstart[N] = E;
}

// ---------------- permute edges into CSR ----------------
__global__ void perm_k(const int* __restrict__ src, const int* __restrict__ dst, int E) {
    int e = blockIdx.x * blockDim.x + threadIdx.x;
    if (e < E) {
        int d = dst[e];
        int pos = atomicAdd(&g_cursor[d], 1);
        g_esrc[pos] = src[e];
    }
}

// ---------------- GEMM: g_t[n] = fp16( dinv[n] * (A @ W)[n] )
// A = x (layer 0) or relu(g_acc * scale + shift) (layers > 0, fused BN+ReLU)
// 128x64 tile, 128 threads, 8x8 per-thread register tile, f32x2 FFMA2
__global__ void gemm128_k(const float* __restrict__ X, const float* __restrict__ W,
                          int layer, int N) {
    __shared__ __align__(16) float As[64][128];  // As[k][r], 32KB
    __shared__ __align__(16) float Bs[64][64];   // Bs[k][c], 16KB
    int t = threadIdx.x;            // 128 threads
    int row0 = blockIdx.x * 128;

    // load W tile: 1024 float4
    #pragma unroll
    for (int i = t; i < 1024; i += 128)
        ((float4*)Bs)[i] = ((const float4*)W)[i];

    // load A: thread t owns global row row0+t; 16 float4 per row, store transposed
    {
        int gr = row0 + t;
        bool valid = (gr < N);
        if (layer == 0) {
            const float4* arow = (const float4*)(X + (size_t)gr * 64);
            #pragma unroll
            for (int it = 0; it < 16; it++) {
                float4 v = valid ? arow[it] : make_float4(0.f, 0.f, 0.f, 0.f);
                As[it * 4 + 0][t] = v.x;
                As[it * 4 + 1][t] = v.y;
                As[it * 4 + 2][t] = v.z;
                As[it * 4 + 3][t] = v.w;
            }
        } else {
            const float4* arow = (const float4*)(g_acc + (size_t)gr * 64);
            #pragma unroll
            for (int it = 0; it < 16; it++) {
                float4 v = make_float4(0.f, 0.f, 0.f, 0.f);
                if (valid) {
                    float4 a = arow[it];
                    float4 sc = ((const float4*)g_scale)[it];
                    float4 sh = ((const float4*)g_shift)[it];
                    v.x = fmaxf(a.x * sc.x + sh.x, 0.f);
                    v.y = fmaxf(a.y * sc.y + sh.y, 0.f);
                    v.z = fmaxf(a.z * sc.z + sh.z, 0.f);
                    v.w = fmaxf(a.w * sc.w + sh.w, 0.f);
                }
                As[it * 4 + 0][t] = v.x;
                As[it * 4 + 1][t] = v.y;
                As[it * 4 + 2][t] = v.z;
                As[it * 4 + 3][t] = v.w;
            }
        }
    }
    __syncthreads();

    int tx = t & 7, ty = t >> 3;       // 8 col-groups x 16 row-groups
    int r0 = ty * 8, c0 = tx * 8;

    unsigned long long acc[4][8];      // [row-pair][col]
    #pragma unroll
    for (int p = 0; p < 4; p++)
        #pragma unroll
        for (int j = 0; j < 8; j++) acc[p][j] = 0ULL;

    #pragma unroll 4
    for (int k = 0; k < 64; k++) {
        float4 a0 = *(const float4*)&As[k][r0];
        float4 a1 = *(const float4*)&As[k][r0 + 4];
        float4 b0 = *(const float4*)&Bs[k][c0];
        float4 b1 = *(const float4*)&Bs[k][c0 + 4];
        unsigned long long ap[4];
        ap[0] = pk2(a0.x, a0.y); ap[1] = pk2(a0.z, a0.w);
        ap[2] = pk2(a1.x, a1.y); ap[3] = pk2(a1.z, a1.w);
        unsigned long long bb[8];
        bb[0] = pk2(b0.x, b0.x); bb[1] = pk2(b0.y, b0.y);
        bb[2] = pk2(b0.z, b0.z); bb[3] = pk2(b0.w, b0.w);
        bb[4] = pk2(b1.x, b1.x); bb[5] = pk2(b1.y, b1.y);
        bb[6] = pk2(b1.z, b1.z); bb[7] = pk2(b1.w, b1.w);
        #pragma unroll
        for (int p = 0; p < 4; p++)
            #pragma unroll
            for (int j = 0; j < 8; j++)
                fma2(acc[p][j], ap[p], bb[j]);
    }

    // store: unpack row pairs, scale by dinv, convert to fp16 (uint4 = 8 halfs)
    #pragma unroll
    for (int p = 0; p < 4; p++) {
        int re = row0 + r0 + 2 * p;      // even row
        int ro = re + 1;                 // odd row
        float2 v[8];
        #pragma unroll
        for (int j = 0; j < 8; j++) v[j] = upk2(acc[p][j]);
        if (re < N) {
            float dv = g_dinv[re];
            __half2 h0 = __floats2half2_rn(v[0].x * dv, v[1].x * dv);
            __half2 h1 = __floats2half2_rn(v[2].x * dv, v[3].x * dv);
            __half2 h2 = __floats2half2_rn(v[4].x * dv, v[5].x * dv);
            __half2 h3 = __floats2half2_rn(v[6].x * dv, v[7].x * dv);
            uint4 o;
            o.x = *(unsigned*)&h0; o.y = *(unsigned*)&h1;
            o.z = *(unsigned*)&h2; o.w = *(unsigned*)&h3;
            *((uint4*)(g_t + (size_t)re * 64 + c0)) = o;
        }
        if (ro < N) {
            float dv = g_dinv[ro];
            __half2 h0 = __floats2half2_rn(v[0].y * dv, v[1].y * dv);
            __half2 h1 = __floats2half2_rn(v[2].y * dv, v[3].y * dv);
            __half2 h2 = __floats2half2_rn(v[4].y * dv, v[5].y * dv);
            __half2 h3 = __floats2half2_rn(v[6].y * dv, v[7].y * dv);
            uint4 o;
            o.x = *(unsigned*)&h0; o.y = *(unsigned*)&h1;
            o.z = *(unsigned*)&h2; o.w = *(unsigned*)&h3;
            *((uint4*)(g_t + (size_t)ro * 64 + c0)) = o;
        }
    }
}

// ---------------- fp16 row accumulate helper ----------------
__device__ __forceinline__ void h8_add(uint4 raw, float2& f0, float2& f1,
                                       float2& f2, float2& f3) {
    float2 a = __half22float2(*(__half2*)&raw.x);
    float2 b = __half22float2(*(__half2*)&raw.y);
    float2 c = __half22float2(*(__half2*)&raw.z);
    float2 d = __half22float2(*(__half2*)&raw.w);
    f0.x += a.x; f0.y += a.y;
    f1.x += b.x; f1.y += b.y;
    f2.x += c.x; f2.y += c.y;
    f3.x += d.x; f3.y += d.y;
}

// ---------------- CSR gather (fp16 src rows) + fused BN partial stats --------
// acc[d] = dinv[d]*(sum g_t[src] + g_t[d]) + b ; 8 lanes per node
__global__ void gather8_k(const float* __restrict__ b, int N) {
    int idx = blockIdx.x * blockDim.x + threadIdx.x;
    int node = idx >> 3;
    int lane = idx & 7;          // owns cols lane*8 .. lane*8+7

    float2 f0 = make_float2(0.f, 0.f), f1 = f0, f2 = f0, f3 = f0;
    float o0 = 0.f, o1 = 0.f, o2 = 0.f, o3 = 0.f,
          o4 = 0.f, o5 = 0.f, o6 = 0.f, o7 = 0.f;

    if (node < N) {
        // self loop
        uint4 raw = *((const uint4*)(g_t + (size_t)node * 64) + lane);
        h8_add(raw, f0, f1, f2, f3);

        int beg = g_rowstart[node];
        int end = g_rowstart[node + 1];
        int k = beg;
        #pragma unroll 1
        for (; k + 8 <= end; k += 8) {
            uint4 r0 = __ldg((const uint4*)(g_t + (size_t)g_esrc[k + 0] * 64) + lane);
            uint4 r1 = __ldg((const uint4*)(g_t + (size_t)g_esrc[k + 1] * 64) + lane);
            uint4 r2 = __ldg((const uint4*)(g_t + (size_t)g_esrc[k + 2] * 64) + lane);
            uint4 r3 = __ldg((const uint4*)(g_t + (size_t)g_esrc[k + 3] * 64) + lane);
            uint4 r4 = __ldg((const uint4*)(g_t + (size_t)g_esrc[k + 4] * 64) + lane);
            uint4 r5 = __ldg((const uint4*)(g_t + (size_t)g_esrc[k + 5] * 64) + lane);
            uint4 r6 = __ldg((const uint4*)(g_t + (size_t)g_esrc[k + 6] * 64) + lane);
            uint4 r7 = __ldg((const uint4*)(g_t + (size_t)g_esrc[k + 7] * 64) + lane);
            h8_add(r0, f0, f1, f2, f3); h8_add(r1, f0, f1, f2, f3);
            h8_add(r2, f0, f1, f2, f3); h8_add(r3, f0, f1, f2, f3);
            h8_add(r4, f0, f1, f2, f3); h8_add(r5, f0, f1, f2, f3);
            h8_add(r6, f0, f1, f2, f3); h8_add(r7, f0, f1, f2, f3);
        }
        for (; k < end; k++) {
            uint4 r = __ldg((const uint4*)(g_t + (size_t)g_esrc[k] * 64) + lane);
            h8_add(r, f0, f1, f2, f3);
        }

        float dv = g_dinv[node];
        float4 bb0 = ((const float4*)b)[lane * 2 + 0];
        float4 bb1 = ((const float4*)b)[lane * 2 + 1];
        o0 = f0.x * dv + bb0.x; o1 = f0.y * dv + bb0.y;
        o2 = f1.x * dv + bb0.z; o3 = f1.y * dv + bb0.w;
        o4 = f2.x * dv + bb1.x; o5 = f2.y * dv + bb1.y;
        o6 = f3.x * dv + bb1.z; o7 = f3.y * dv + bb1.w;

        float* dst = g_acc + (size_t)node * 64 + lane * 8;
        *(float4*)(dst + 0) = make_float4(o0, o1, o2, o3);
        *(float4*)(dst + 4) = make_float4(o4, o5, o6, o7);
    }

    // --- fused BN partial stats: 32 nodes x 64 cols per block ---
    __shared__ float ssum[32][64];
    __shared__ float ssq[32][64];
    int slot = threadIdx.x >> 3;
    int c = lane * 8;
    ssum[slot][c + 0] = o0; ssq[slot][c + 0] = o0 * o0;
    ssum[slot][c + 1] = o1; ssq[slot][c + 1] = o1 * o1;
    ssum[slot][c + 2] = o2; ssq[slot][c + 2] = o2 * o2;
    ssum[slot][c + 3] = o3; ssq[slot][c + 3] = o3 * o3;
    ssum[slot][c + 4] = o4; ssq[slot][c + 4] = o4 * o4;
    ssum[slot][c + 5] = o5; ssq[slot][c + 5] = o5 * o5;
    ssum[slot][c + 6] = o6; ssq[slot][c + 6] = o6 * o6;
    ssum[slot][c + 7] = o7; ssq[slot][c + 7] = o7 * o7;
    __syncthreads();

    if (threadIdx.x < 64) {
        float s = 0.f, q = 0.f;
        #pragma unroll
        for (int r = 0; r < 32; r++) { s += ssum[r][threadIdx.x]; q += ssq[r][threadIdx.x]; }
        g_psum[blockIdx.x * DD + threadIdx.x] = s;
        g_psq[blockIdx.x * DD + threadIdx.x] = q;
    }
}

// ---------------- BN finalize: 64 blocks, one column each ----------------
__global__ void bn_final_k(const float* __restrict__ gamma,
                           const float* __restrict__ beta, int N, int nblocks) {
    int c = blockIdx.x;
    int t = threadIdx.x;     // 256
    float s = 0.f, q = 0.f;
    for (int b = t; b < nblocks; b += 256) {
        s += g_psum[b * DD + c];
        q += g_psq[b * DD + c];
    }
    __shared__ float sh_s[256], sh_q[256];
    sh_s[t] = s; sh_q[t] = q;
    __syncthreads();
    #pragma unroll
    for (int o = 128; o > 0; o >>= 1) {
        if (t < o) { sh_s[t] += sh_s[t + o]; sh_q[t] += sh_q[t + o]; }
        __syncthreads();
    }
    if (t == 0) {
        float inv_n = 1.0f / (float)N;
        float m = sh_s[0] * inv_n;
        float v = sh_q[0] * inv_n - m * m;
        float sc = gamma[c] * rsqrtf(v + BN_EPS);
        g_scale[c] = sc;
        g_shift[c] = beta[c] - m * sc;
    }
}

// ---------------- mean pool (fused BN+ReLU of last layer) ----------------
__global__ void pool_k(const int* __restrict__ batch, float* __restrict__ out, int N) {
    int col = threadIdx.x;  // 64 threads
    int start = blockIdx.x * 128;
    if (start >= N) return;
    int end = min(start + 128, N);
    float sc = g_scale[col];
    float sh = g_shift[col];
    int g = batch[start];
    float s = 0.f;
    float cnt = 0.f;
    for (int n = start; n < end; n++) {
        int gn = batch[n];
        if (gn != g) {
            atomicAdd(&out[g * 64 + col], s);
            if (col == 0) atomicAdd(&g_gcnt[g], cnt);
            s = 0.f; cnt = 0.f; g = gn;
        }
        float a = g_acc[(size_t)n * 64 + col];
        s += fmaxf(a * sc + sh, 0.f);
        cnt += 1.f;
    }
    atomicAdd(&out[g * 64 + col], s);
    if (col == 0) atomicAdd(&g_gcnt[g], cnt);
}

__global__ void scale_out_k(float* out) {
    int i = blockIdx.x * blockDim.x + threadIdx.x;
    if (i < GG * DD) {
        float c = g_gcnt[i >> 6];
        out[i] /= fmaxf(c, 1.f);
    }
}

// ---------------- host launch ----------------
extern "C" void kernel_launch(void* const* d_in, const int* in_sizes, int n_in,
                              void* d_out, int out_size) {
    const float* x      = (const float*)d_in[0];
    const int*   ei     = (const int*)d_in[1];     // int32 (JAX x64 disabled)
    const int*   batch  = (const int*)d_in[2];     // int32
    const float* Ws     = (const float*)d_in[3];
    const float* bs     = (const float*)d_in[4];
    const float* gammas = (const float*)d_in[5];
    const float* betas  = (const float*)d_in[6];
    float*       out    = (float*)d_out;

    int N = in_sizes[0] / DD;   // 100000
    int E = in_sizes[1] / 2;    // 1600000
    const int* src = ei;
    const int* dst = ei + E;

    int tb = 256;
    int nBlk  = (N + tb - 1) / tb;
    int eBlk  = (E + tb - 1) / tb;
    int gaBlk = (N * 8 + tb - 1) / tb;         // 3125
    int gmBlk = (N + 127) / 128;               // 782
    int nScanBlk = (N + SCAN_BS - 1) / SCAN_BS;

    init_k<<<nBlk, tb>>>(out, N);
    deg_k<<<eBlk, tb>>>(dst, E);
    scan1_k<<<nScanBlk, SCAN_BS>>>(N);
    scan3_k<<<nBlk, tb>>>(N, E, nScanBlk);
    perm_k<<<eBlk, tb>>>(src, dst, E);

    for (int l = 0; l < 3; l++) {
        gemm128_k<<<gmBlk, 128>>>(x, Ws + l * DD * DD, l, N);
        gather8_k<<<gaBlk, tb>>>(bs + l * DD, N);
        bn_final_k<<<64, 256>>>(gammas + l * DD, betas + l * DD, N, gaBlk);
    }

    pool_k<<<(N + 127) / 128, 64>>>(batch, out, N);
    scale_out_k<<<(GG * DD + tb - 1) / tb, tb>>>(out);
}